// round 15
// baseline (speedup 1.0000x reference)
#include <cuda_runtime.h>
#include <cuda_pipeline.h>
#include <cstdint>
#include <math.h>

#define BATCH 4
#define C     256
#define HEADS 4
#define DIM   64
#define NPIX  4096
#define CPG   32

__device__ uint32_t g_xnb [BATCH * C * NPIX / 2];     // xn bf16 [b][c][pix/2]
__device__ uint32_t g_qkvb[BATCH * 3 * C * NPIX / 2]; // qkv bf16 [b][o][pix/2]
__device__ unsigned short g_aob[BATCH * C * NPIX];    // attn out bf16 [b][c][pix]
__device__ uint32_t g_wqb[3 * C * C / 2];             // w_qkv bf16 [m][k/2]
__device__ uint32_t g_wpb[C * C / 2];                 // w_proj bf16 [m][k/2]
__device__ float    g_gnp[256 * 2];                   // groupnorm partials

// ---------------------------------------------------------------- helpers
__device__ __forceinline__ uint32_t packbf(float lo, float hi) {
    uint32_t r;
    asm("cvt.rn.bf16x2.f32 %0, %1, %2;" : "=r"(r) : "f"(hi), "f"(lo));
    return r;
}
__device__ __forceinline__ unsigned short bf16c(float f) {
    unsigned short h;
    asm("cvt.rn.bf16.f32 %0, %1;" : "=h"(h) : "f"(f));
    return h;
}
__device__ __forceinline__ float ubf(unsigned short u) {
    return __uint_as_float(((uint32_t)u) << 16);
}
__device__ __forceinline__ float ex2(float x) {
    float r;
    asm("ex2.approx.f32 %0, %1;" : "=f"(r) : "f"(x));
    return r;
}
__device__ __forceinline__ uint32_t smem_u32(const void* p) {
    uint32_t a;
    asm("{ .reg .u64 t; cvta.to.shared.u64 t, %1; cvt.u32.u64 %0, t; }" : "=r"(a) : "l"(p));
    return a;
}
__device__ __forceinline__ void mma_bf16(
    float& d0, float& d1, float& d2, float& d3,
    uint32_t a0, uint32_t a1, uint32_t a2, uint32_t a3,
    uint32_t b0, uint32_t b1)
{
    asm volatile(
        "mma.sync.aligned.m16n8k16.row.col.f32.bf16.bf16.f32 "
        "{%0,%1,%2,%3}, {%4,%5,%6,%7}, {%8,%9}, {%0,%1,%2,%3};"
        : "+f"(d0), "+f"(d1), "+f"(d2), "+f"(d3)
        : "r"(a0), "r"(a1), "r"(a2), "r"(a3), "r"(b0), "r"(b1));
}
__device__ __forceinline__ void ldsm4(uint32_t& r0, uint32_t& r1,
                                      uint32_t& r2, uint32_t& r3, uint32_t a)
{
    asm volatile("ldmatrix.sync.aligned.m8n8.x4.shared.b16 {%0,%1,%2,%3}, [%4];"
        : "=r"(r0), "=r"(r1), "=r"(r2), "=r"(r3) : "r"(a));
}
__device__ __forceinline__ void ldsm4t(uint32_t& r0, uint32_t& r1,
                                       uint32_t& r2, uint32_t& r3, uint32_t a)
{
    asm volatile("ldmatrix.sync.aligned.m8n8.x4.trans.shared.b16 {%0,%1,%2,%3}, [%4];"
        : "=r"(r0), "=r"(r1), "=r"(r2), "=r"(r3) : "r"(a));
}

// ------------ launch 1: GN partial stats (blocks 0..255) + weight bf16 pack
__global__ void __launch_bounds__(256) prep_kernel(
    const float* __restrict__ x, const float* __restrict__ wq,
    const float* __restrict__ wp, float* __restrict__ part,
    uint32_t* __restrict__ oq, uint32_t* __restrict__ op)
{
    const int bid = blockIdx.x, tid = threadIdx.x;
    if (bid < 256) {
        const float4* xp = (const float4*)x + (size_t)bid * 4096;
        float s = 0.f, ss = 0.f;
#pragma unroll
        for (int i = 0; i < 16; ++i) {
            float4 v = xp[tid + i * 256];
            s += (v.x + v.y) + (v.z + v.w);
            ss = fmaf(v.x, v.x, ss); ss = fmaf(v.y, v.y, ss);
            ss = fmaf(v.z, v.z, ss); ss = fmaf(v.w, v.w, ss);
        }
        __shared__ float rs[8], rss[8];
#pragma unroll
        for (int o = 16; o > 0; o >>= 1) {
            s  += __shfl_xor_sync(~0u, s, o);
            ss += __shfl_xor_sync(~0u, ss, o);
        }
        if ((tid & 31) == 0) { rs[tid >> 5] = s; rss[tid >> 5] = ss; }
        __syncthreads();
        if (tid == 0) {
            float a = 0.f, a2 = 0.f;
#pragma unroll
            for (int i = 0; i < 8; ++i) { a += rs[i]; a2 += rss[i]; }
            part[bid * 2 + 0] = a;
            part[bid * 2 + 1] = a2;
        }
    } else if (bid < 640) {
        const int i = (bid - 256) * 256 + tid;
        oq[i] = packbf(wq[2 * i], wq[2 * i + 1]);
    } else {
        const int i = (bid - 640) * 256 + tid;
        op[i] = packbf(wp[2 * i], wp[2 * i + 1]);
    }
}

// ------------ launch 2: finalize stats (redundant per block) + apply -> bf16
__global__ void __launch_bounds__(256) gn_apply_kernel(
    const float* __restrict__ x, const float* __restrict__ gamma,
    const float* __restrict__ beta, const float* __restrict__ part,
    uint32_t* __restrict__ xnb)
{
    const int gi = blockIdx.x >> 3, sl = blockIdx.x & 7;
    const int g = gi & 7;
    __shared__ float st[2];
    if (threadIdx.x == 0) {
        float s = 0.f, ss = 0.f;
#pragma unroll
        for (int i = 0; i < 8; ++i) {
            s  += part[(gi * 8 + i) * 2 + 0];
            ss += part[(gi * 8 + i) * 2 + 1];
        }
        const float inv_n = 1.0f / (float)(CPG * NPIX);
        const float mean = s * inv_n;
        st[0] = mean;
        st[1] = rsqrtf(ss * inv_n - mean * mean + 1e-5f);
    }
    __syncthreads();
    const float mean = st[0], rstd = st[1];
    const float4* xp = (const float4*)x + (size_t)gi * 32768 + sl * 4096;
    uint32_t* op = xnb + (size_t)gi * 65536 + sl * 8192;
    const int tid = threadIdx.x;
#pragma unroll
    for (int i = 0; i < 16; ++i) {
        const int idx = tid + i * 256;
        const int c = g * CPG + ((sl * 4096 + idx) >> 10);
        const float ga = gamma[c] * rstd, be = beta[c] - mean * ga;
        float4 v = xp[idx];
        uint2 o;
        o.x = packbf(fmaf(v.x, ga, be), fmaf(v.y, ga, be));
        o.y = packbf(fmaf(v.z, ga, be), fmaf(v.w, ga, be));
        *(uint2*)&op[idx * 2] = o;
    }
}

// ------------ bf16 GEMM, 4-stage cp.async pipeline.
// MODE 0: out packed bf16.  MODE 1: out fp32 + bias + residual.
#define QAP 12
#define QBP 68
#define QA_T (128 * QAP)
#define QB_T (16 * QBP)

template<int MODE>
__global__ void __launch_bounds__(256) bgemm_kernel(
    const uint32_t* __restrict__ W, const uint32_t* __restrict__ XN,
    const float* __restrict__ bias, const float* __restrict__ R,
    void* __restrict__ CoutV, int M)
{
    const int N = NPIX;
    const int n0 = blockIdx.x * 128, m0 = blockIdx.y * 128, bz = blockIdx.z;
    const uint32_t* Xb = XN + (size_t)bz * C * NPIX / 2;

    __shared__ uint32_t smA[4 * QA_T];
    __shared__ uint32_t smB[4 * QB_T];
    const uint32_t sA = smem_u32(smA), sB = smem_u32(smB);

    const int tid = threadIdx.x;
    const int lane = tid & 31, w = tid >> 5;
    const int qr = lane >> 2, qc = lane & 3;
    const int wm = (w >> 2) * 64, wn = (w & 3) * 32;

    auto fill = [&](int buf, int k0) {
        uint32_t* as = smA + buf * QA_T;
        uint32_t* bs = smB + buf * QB_T;
        {
            int row = tid >> 1, half = (tid & 1) << 2;
            __pipeline_memcpy_async(as + row * QAP + half,
                W + (size_t)(m0 + row) * 128 + (k0 >> 1) + half, 16);
        }
        {
            int row = tid >> 4, ch = (tid & 15) << 2;
            __pipeline_memcpy_async(bs + row * QBP + ch,
                Xb + (size_t)(k0 + row) * 2048 + (n0 >> 1) + ch, 16);
        }
        __pipeline_commit();
    };

    float acc[4][4][4];
#pragma unroll
    for (int mf = 0; mf < 4; ++mf)
#pragma unroll
        for (int nf = 0; nf < 4; ++nf)
#pragma unroll
            for (int i = 0; i < 4; ++i) acc[mf][nf][i] = 0.f;

    const uint32_t aoff = (lane & 15) * 48 + (lane >> 4) * 16;
    const uint32_t boff = (lane & 7) * 272 + (lane >> 3) * 16 + wn * 2;

    fill(0, 0); fill(1, 16); fill(2, 32);
#pragma unroll 1
    for (int kc = 0; kc < 16; ++kc) {
        __pipeline_wait_prior(2);
        __syncthreads();
        if (kc + 3 < 16) fill((kc + 3) & 3, (kc + 3) << 4);
        else __pipeline_commit();
        const uint32_t asb = sA + ((kc & 3) * QA_T) * 4 + aoff;
        const uint32_t bsb = sB + ((kc & 3) * QB_T) * 4 + boff;

        uint32_t af[4][4], bf[2][4];
#pragma unroll
        for (int mf = 0; mf < 4; ++mf)
            ldsm4(af[mf][0], af[mf][1], af[mf][2], af[mf][3],
                  asb + (wm + mf * 16) * 48);
#pragma unroll
        for (int j = 0; j < 2; ++j)
            ldsm4t(bf[j][0], bf[j][1], bf[j][2], bf[j][3],
                   bsb + (j * 8) * 272);
#pragma unroll
        for (int mf = 0; mf < 4; ++mf)
#pragma unroll
            for (int nf = 0; nf < 4; ++nf)
                mma_bf16(acc[mf][nf][0], acc[mf][nf][1],
                         acc[mf][nf][2], acc[mf][nf][3],
                         af[mf][0], af[mf][1], af[mf][2], af[mf][3],
                         bf[0][nf], bf[1][nf]);
    }

#pragma unroll
    for (int mf = 0; mf < 4; ++mf) {
        const int r0 = m0 + wm + mf * 16 + qr;
        const float bs0 = bias[r0], bs1 = bias[r0 + 8];
#pragma unroll
        for (int nf = 0; nf < 4; ++nf) {
            const int col = n0 + wn + nf * 8 + 2 * qc;
            float o0 = acc[mf][nf][0] + bs0;
            float o1 = acc[mf][nf][1] + bs0;
            float o2 = acc[mf][nf][2] + bs1;
            float o3 = acc[mf][nf][3] + bs1;
            if (MODE == 1) {
                const float* Rb = R + (size_t)bz * M * N;
                const float* rp0 = &Rb[(size_t)r0 * N + col];
                const float* rp1 = &Rb[(size_t)(r0 + 8) * N + col];
                o0 += rp0[0]; o1 += rp0[1]; o2 += rp1[0]; o3 += rp1[1];
                float* Cb = (float*)CoutV + (size_t)bz * M * N;
                float2 lo; lo.x = o0; lo.y = o1;
                float2 hi; hi.x = o2; hi.y = o3;
                *(float2*)&Cb[(size_t)r0 * N + col] = lo;
                *(float2*)&Cb[(size_t)(r0 + 8) * N + col] = hi;
            } else {
                uint32_t* Cb = (uint32_t*)CoutV + (size_t)bz * M * N / 2;
                Cb[(size_t)r0 * 2048 + (col >> 1)] = packbf(o0, o1);
                Cb[(size_t)(r0 + 8) * 2048 + (col >> 1)] = packbf(o2, o3);
            }
        }
    }
}

// ------------ launch 4: attention (round-11 base; restructured kk body)
// V ldsm issued first (latency hidden under QK); QK accumulation chains
// split depth 4 -> 2 (ca/cb partials, FADD merge). 2-stage K/V buffer.
#define AP   68                     // pitch in u32 (Bk/2 + 4)
#define AT   (64 * AP)              // one tensor tile (u32)
#define ABUF (2 * AT)               // K + V per stage
#define ASM_WORDS (2 * ABUF)        // 69632 B

__device__ __forceinline__ void a_fill(
    uint32_t* sm, const uint32_t* kz, const uint32_t* vz, int buf, int j0, int tid)
{
    uint32_t* kbuf = sm + buf * ABUF;
    uint32_t* vbuf = kbuf + AT;
#pragma unroll
    for (int i = 0; i < 4; ++i) {
        int lin = tid + i * 256;
        int row = lin >> 4, ch = (lin & 15) << 2;
        __pipeline_memcpy_async(kbuf + row * AP + ch,
                                kz + (size_t)row * 2048 + (j0 >> 1) + ch, 16);
    }
#pragma unroll
    for (int i = 0; i < 4; ++i) {
        int lin = tid + i * 256;
        int row = lin >> 4, ch = (lin & 15) << 2;
        __pipeline_memcpy_async(vbuf + row * AP + ch,
                                vz + (size_t)row * 2048 + (j0 >> 1) + ch, 16);
    }
    __pipeline_commit();
}

__global__ void __launch_bounds__(256, 2) attn_mma_kernel(
    const uint32_t* __restrict__ qkvb, unsigned short* __restrict__ aob)
{
    extern __shared__ uint32_t sm[];
    const uint32_t sbase = smem_u32(sm);
    const int tid = threadIdx.x;
    const int lane = tid & 31, w = tid >> 5;
    const int qr = lane >> 2, qc = lane & 3;
    const int i0 = blockIdx.x * 128, h = blockIdx.y, b = blockIdx.z;

    const unsigned short* qp16 =
        (const unsigned short*)qkvb + ((size_t)b * 3 * C + h * DIM) * NPIX;
    const uint32_t* kz = qkvb + ((size_t)b * 3 * C + C + h * DIM) * 2048;
    const uint32_t* vz = qkvb + ((size_t)b * 3 * C + 2 * C + h * DIM) * 2048;

    const float QS = 0.125f * 1.44269504088896341f;
    const int q0 = i0 + w * 16 + qr;
    uint32_t qa[4][4];
#pragma unroll
    for (int kbk = 0; kbk < 4; ++kbk) {
        const int d0 = kbk * 16 + 2 * qc;
#pragma unroll
        for (int half = 0; half < 2; ++half) {
            const int d = d0 + half * 8;
            qa[kbk][half * 2 + 0] =
                packbf(ubf(qp16[(size_t)d * NPIX + q0]) * QS,
                       ubf(qp16[(size_t)(d + 1) * NPIX + q0]) * QS);
            qa[kbk][half * 2 + 1] =
                packbf(ubf(qp16[(size_t)d * NPIX + q0 + 8]) * QS,
                       ubf(qp16[(size_t)(d + 1) * NPIX + q0 + 8]) * QS);
        }
    }

    float oc[8][4];
#pragma unroll
    for (int nv = 0; nv < 8; ++nv)
#pragma unroll
        for (int i = 0; i < 4; ++i) oc[nv][i] = 0.f;
    float l0 = 0.f, l1 = 0.f;

    const uint32_t lmoff = lane * AP * 4;   // lane = d row

    a_fill(sm, kz, vz, 0, 0, tid);

#pragma unroll 1
    for (int t = 0; t < 32; ++t) {
        __pipeline_wait_prior(0);
        __syncthreads();
        if (t + 1 < 32) a_fill(sm, kz, vz, (t + 1) & 1, (t + 1) << 7, tid);

        const uint32_t ksb = sbase + ((t & 1) * ABUF) * 4 + lmoff;
        const uint32_t vsb = ksb + AT * 4;

#pragma unroll
        for (int kk = 0; kk < 8; ++kk) {
            // 1) V frags FIRST — consumed only after exp, latency hides under QK
            uint32_t vf[2][8];
#pragma unroll
            for (int j = 0; j < 2; ++j) {
                const uint32_t rb = vsb + (kk * 16 + j * 8) * 2;
                ldsm4(vf[j][0], vf[j][1], vf[j][2], vf[j][3], rb);
                ldsm4(vf[j][4], vf[j][5], vf[j][6], vf[j][7], rb + 32 * AP * 4);
            }
            // 2) K frags
            uint32_t kf[2][8];
#pragma unroll
            for (int j = 0; j < 2; ++j) {
                const uint32_t rb = ksb + (kk * 16 + j * 8) * 2;
                ldsm4t(kf[j][0], kf[j][1], kf[j][2], kf[j][3], rb);
                ldsm4t(kf[j][4], kf[j][5], kf[j][6], kf[j][7], rb + 32 * AP * 4);
            }
            // 3) QK with depth-2 accumulation chains (ca/cb partials)
            float ca[2][4] = {}, cb[2][4] = {};
#pragma unroll
            for (int j = 0; j < 2; ++j) {
                mma_bf16(ca[j][0], ca[j][1], ca[j][2], ca[j][3],
                         qa[0][0], qa[0][1], qa[0][2], qa[0][3],
                         kf[j][0], kf[j][1]);
                mma_bf16(cb[j][0], cb[j][1], cb[j][2], cb[j][3],
                         qa[1][0], qa[1][1], qa[1][2], qa[1][3],
                         kf[j][2], kf[j][3]);
                mma_bf16(ca[j][0], ca[j][1], ca[j][2], ca[j][3],
                         qa[2][0], qa[2][1], qa[2][2], qa[2][3],
                         kf[j][4], kf[j][5]);
                mma_bf16(cb[j][0], cb[j][1], cb[j][2], cb[j][3],
                         qa[3][0], qa[3][1], qa[3][2], qa[3][3],
                         kf[j][6], kf[j][7]);
            }
            // 4) merge + exp + pack
            float p00 = ex2(ca[0][0] + cb[0][0]);
            float p01 = ex2(ca[0][1] + cb[0][1]);
            float p02 = ex2(ca[0][2] + cb[0][2]);
            float p03 = ex2(ca[0][3] + cb[0][3]);
            float p10 = ex2(ca[1][0] + cb[1][0]);
            float p11 = ex2(ca[1][1] + cb[1][1]);
            float p12 = ex2(ca[1][2] + cb[1][2]);
            float p13 = ex2(ca[1][3] + cb[1][3]);
            l0 += (p00 + p01) + (p10 + p11);
            l1 += (p02 + p03) + (p12 + p13);
            const uint32_t a0 = packbf(p00, p01);
            const uint32_t a1 = packbf(p02, p03);
            const uint32_t a2 = packbf(p10, p11);
            const uint32_t a3 = packbf(p12, p13);

            // 5) PV
#pragma unroll
            for (int nv = 0; nv < 8; ++nv)
                mma_bf16(oc[nv][0], oc[nv][1], oc[nv][2], oc[nv][3],
                         a0, a1, a2, a3, vf[0][nv], vf[1][nv]);
        }
    }

    l0 += __shfl_xor_sync(~0u, l0, 1); l0 += __shfl_xor_sync(~0u, l0, 2);
    l1 += __shfl_xor_sync(~0u, l1, 1); l1 += __shfl_xor_sync(~0u, l1, 2);
    const float inv0 = 1.0f / l0, inv1 = 1.0f / l1;

    unsigned short* aop = aob + ((size_t)b * C + h * DIM) * NPIX;
#pragma unroll
    for (int nv = 0; nv < 8; ++nv) {
        const int d = nv * 8 + 2 * qc;
        aop[(size_t)d * NPIX + q0]           = bf16c(oc[nv][0] * inv0);
        aop[(size_t)(d + 1) * NPIX + q0]     = bf16c(oc[nv][1] * inv0);
        aop[(size_t)d * NPIX + q0 + 8]       = bf16c(oc[nv][2] * inv1);
        aop[(size_t)(d + 1) * NPIX + q0 + 8] = bf16c(oc[nv][3] * inv1);
    }
}

// ---------------------------------------------------------------- Launch
extern "C" void kernel_launch(void* const* d_in, const int* in_sizes, int n_in,
                              void* d_out, int out_size)
{
    const float* x      = (const float*)d_in[0];
    const float* gamma  = (const float*)d_in[1];
    const float* beta   = (const float*)d_in[2];
    const float* w_qkv  = (const float*)d_in[3];
    const float* b_qkv  = (const float*)d_in[4];
    const float* w_proj = (const float*)d_in[5];
    const float* b_proj = (const float*)d_in[6];
    float* out = (float*)d_out;

    float *gnp;
    uint32_t *xnb, *qkvb, *wqb, *wpb;
    unsigned short* aob;
    cudaGetSymbolAddress((void**)&xnb,  g_xnb);
    cudaGetSymbolAddress((void**)&qkvb, g_qkvb);
    cudaGetSymbolAddress((void**)&aob,  g_aob);
    cudaGetSymbolAddress((void**)&wqb,  g_wqb);
    cudaGetSymbolAddress((void**)&wpb,  g_wpb);
    cudaGetSymbolAddress((void**)&gnp,  g_gnp);

    static bool attr_set = false;
    if (!attr_set) {
        cudaFuncSetAttribute(attn_mma_kernel,
                             cudaFuncAttributeMaxDynamicSharedMemorySize,
                             ASM_WORDS * 4);
        attr_set = true;
    }

    // 1: GN partial stats + weight packing
    prep_kernel<<<768, 256>>>(x, w_qkv, w_proj, gnp, wqb, wpb);
    // 2: GN finalize + apply -> xn bf16
    gn_apply_kernel<<<256, 256>>>(x, gamma, beta, gnp, xnb);
    // 3: QKV GEMM (bf16 in, bf16 packed out)
    {
        dim3 g(NPIX / 128, (3 * C) / 128, BATCH);
        bgemm_kernel<0><<<g, 256>>>(wqb, xnb, b_qkv, nullptr, qkvb, 3 * C);
    }
    // 4: attention (captured by ncu)
    {
        dim3 g(NPIX / 128, HEADS, BATCH);
        attn_mma_kernel<<<g, 256, ASM_WORDS * 4>>>(qkvb, aob);
    }
    // 5: proj GEMM (bf16 in) + bias + residual -> fp32 out
    {
        dim3 g(NPIX / 128, C / 128, BATCH);
        bgemm_kernel<1><<<g, 256>>>(wpb, (const uint32_t*)aob, b_proj, x, out, C);
    }
}

// round 16
// speedup vs baseline: 1.0937x; 1.0937x over previous
#include <cuda_runtime.h>
#include <cuda_pipeline.h>
#include <cstdint>
#include <math.h>

#define BATCH 4
#define C     256
#define HEADS 4
#define DIM   64
#define NPIX  4096
#define CPG   32

__device__ uint32_t g_xnb [BATCH * C * NPIX / 2];     // xn bf16 [b][c][pix/2]
__device__ uint32_t g_qkvb[BATCH * 3 * C * NPIX / 2]; // qkv bf16 [b][o][pix/2]
__device__ unsigned short g_aob[BATCH * C * NPIX];    // attn out bf16 [b][c][pix]
__device__ uint32_t g_wqb[3 * C * C / 2];             // w_qkv bf16 [m][k/2]
__device__ uint32_t g_wpb[C * C / 2];                 // w_proj bf16 [m][k/2]
__device__ float    g_gnp[256 * 2];                   // groupnorm partials
__device__ float    g_po [2 * BATCH * C * NPIX];      // split-K partial o (fp32)
__device__ float    g_pl [2 * BATCH * HEADS * NPIX];  // split-K partial l

#define PO_OFF (BATCH * C * NPIX)
#define PL_OFF (BATCH * HEADS * NPIX)

// ---------------------------------------------------------------- helpers
__device__ __forceinline__ uint32_t packbf(float lo, float hi) {
    uint32_t r;
    asm("cvt.rn.bf16x2.f32 %0, %1, %2;" : "=r"(r) : "f"(hi), "f"(lo));
    return r;
}
__device__ __forceinline__ float ubf(unsigned short u) {
    return __uint_as_float(((uint32_t)u) << 16);
}
__device__ __forceinline__ float ex2(float x) {
    float r;
    asm("ex2.approx.f32 %0, %1;" : "=f"(r) : "f"(x));
    return r;
}
__device__ __forceinline__ uint32_t smem_u32(const void* p) {
    uint32_t a;
    asm("{ .reg .u64 t; cvta.to.shared.u64 t, %1; cvt.u32.u64 %0, t; }" : "=r"(a) : "l"(p));
    return a;
}
__device__ __forceinline__ void mma_bf16(
    float& d0, float& d1, float& d2, float& d3,
    uint32_t a0, uint32_t a1, uint32_t a2, uint32_t a3,
    uint32_t b0, uint32_t b1)
{
    asm volatile(
        "mma.sync.aligned.m16n8k16.row.col.f32.bf16.bf16.f32 "
        "{%0,%1,%2,%3}, {%4,%5,%6,%7}, {%8,%9}, {%0,%1,%2,%3};"
        : "+f"(d0), "+f"(d1), "+f"(d2), "+f"(d3)
        : "r"(a0), "r"(a1), "r"(a2), "r"(a3), "r"(b0), "r"(b1));
}
__device__ __forceinline__ void ldsm4(uint32_t& r0, uint32_t& r1,
                                      uint32_t& r2, uint32_t& r3, uint32_t a)
{
    asm volatile("ldmatrix.sync.aligned.m8n8.x4.shared.b16 {%0,%1,%2,%3}, [%4];"
        : "=r"(r0), "=r"(r1), "=r"(r2), "=r"(r3) : "r"(a));
}
__device__ __forceinline__ void ldsm4t(uint32_t& r0, uint32_t& r1,
                                       uint32_t& r2, uint32_t& r3, uint32_t a)
{
    asm volatile("ldmatrix.sync.aligned.m8n8.x4.trans.shared.b16 {%0,%1,%2,%3}, [%4];"
        : "=r"(r0), "=r"(r1), "=r"(r2), "=r"(r3) : "r"(a));
}

// ------------ launch 1: GN partial stats (blocks 0..255) + weight bf16 pack
__global__ void __launch_bounds__(256) prep_kernel(
    const float* __restrict__ x, const float* __restrict__ wq,
    const float* __restrict__ wp, float* __restrict__ part,
    uint32_t* __restrict__ oq, uint32_t* __restrict__ op)
{
    const int bid = blockIdx.x, tid = threadIdx.x;
    if (bid < 256) {
        const float4* xp = (const float4*)x + (size_t)bid * 4096;
        float s = 0.f, ss = 0.f;
#pragma unroll
        for (int i = 0; i < 16; ++i) {
            float4 v = xp[tid + i * 256];
            s += (v.x + v.y) + (v.z + v.w);
            ss = fmaf(v.x, v.x, ss); ss = fmaf(v.y, v.y, ss);
            ss = fmaf(v.z, v.z, ss); ss = fmaf(v.w, v.w, ss);
        }
        __shared__ float rs[8], rss[8];
#pragma unroll
        for (int o = 16; o > 0; o >>= 1) {
            s  += __shfl_xor_sync(~0u, s, o);
            ss += __shfl_xor_sync(~0u, ss, o);
        }
        if ((tid & 31) == 0) { rs[tid >> 5] = s; rss[tid >> 5] = ss; }
        __syncthreads();
        if (tid == 0) {
            float a = 0.f, a2 = 0.f;
#pragma unroll
            for (int i = 0; i < 8; ++i) { a += rs[i]; a2 += rss[i]; }
            part[bid * 2 + 0] = a;
            part[bid * 2 + 1] = a2;
        }
    } else if (bid < 640) {
        const int i = (bid - 256) * 256 + tid;
        oq[i] = packbf(wq[2 * i], wq[2 * i + 1]);
    } else {
        const int i = (bid - 640) * 256 + tid;
        op[i] = packbf(wp[2 * i], wp[2 * i + 1]);
    }
}

// ------------ launch 2: finalize stats (redundant per block) + apply -> bf16
__global__ void __launch_bounds__(256) gn_apply_kernel(
    const float* __restrict__ x, const float* __restrict__ gamma,
    const float* __restrict__ beta, const float* __restrict__ part,
    uint32_t* __restrict__ xnb)
{
    const int gi = blockIdx.x >> 3, sl = blockIdx.x & 7;
    const int g = gi & 7;
    __shared__ float st[2];
    if (threadIdx.x == 0) {
        float s = 0.f, ss = 0.f;
#pragma unroll
        for (int i = 0; i < 8; ++i) {
            s  += part[(gi * 8 + i) * 2 + 0];
            ss += part[(gi * 8 + i) * 2 + 1];
        }
        const float inv_n = 1.0f / (float)(CPG * NPIX);
        const float mean = s * inv_n;
        st[0] = mean;
        st[1] = rsqrtf(ss * inv_n - mean * mean + 1e-5f);
    }
    __syncthreads();
    const float mean = st[0], rstd = st[1];
    const float4* xp = (const float4*)x + (size_t)gi * 32768 + sl * 4096;
    uint32_t* op = xnb + (size_t)gi * 65536 + sl * 8192;
    const int tid = threadIdx.x;
#pragma unroll
    for (int i = 0; i < 16; ++i) {
        const int idx = tid + i * 256;
        const int c = g * CPG + ((sl * 4096 + idx) >> 10);
        const float ga = gamma[c] * rstd, be = beta[c] - mean * ga;
        float4 v = xp[idx];
        uint2 o;
        o.x = packbf(fmaf(v.x, ga, be), fmaf(v.y, ga, be));
        o.y = packbf(fmaf(v.z, ga, be), fmaf(v.w, ga, be));
        *(uint2*)&op[idx * 2] = o;
    }
}

// ------------ bf16 GEMM, 4-stage cp.async pipeline.
// MODE 0: out packed bf16.  MODE 1: out fp32 + bias + residual.
#define QAP 12
#define QBP 68
#define QA_T (128 * QAP)
#define QB_T (16 * QBP)

template<int MODE>
__global__ void __launch_bounds__(256) bgemm_kernel(
    const uint32_t* __restrict__ W, const uint32_t* __restrict__ XN,
    const float* __restrict__ bias, const float* __restrict__ R,
    void* __restrict__ CoutV, int M)
{
    const int N = NPIX;
    const int n0 = blockIdx.x * 128, m0 = blockIdx.y * 128, bz = blockIdx.z;
    const uint32_t* Xb = XN + (size_t)bz * C * NPIX / 2;

    __shared__ uint32_t smA[4 * QA_T];
    __shared__ uint32_t smB[4 * QB_T];
    const uint32_t sA = smem_u32(smA), sB = smem_u32(smB);

    const int tid = threadIdx.x;
    const int lane = tid & 31, w = tid >> 5;
    const int qr = lane >> 2, qc = lane & 3;
    const int wm = (w >> 2) * 64, wn = (w & 3) * 32;

    auto fill = [&](int buf, int k0) {
        uint32_t* as = smA + buf * QA_T;
        uint32_t* bs = smB + buf * QB_T;
        {
            int row = tid >> 1, half = (tid & 1) << 2;
            __pipeline_memcpy_async(as + row * QAP + half,
                W + (size_t)(m0 + row) * 128 + (k0 >> 1) + half, 16);
        }
        {
            int row = tid >> 4, ch = (tid & 15) << 2;
            __pipeline_memcpy_async(bs + row * QBP + ch,
                Xb + (size_t)(k0 + row) * 2048 + (n0 >> 1) + ch, 16);
        }
        __pipeline_commit();
    };

    float acc[4][4][4];
#pragma unroll
    for (int mf = 0; mf < 4; ++mf)
#pragma unroll
        for (int nf = 0; nf < 4; ++nf)
#pragma unroll
            for (int i = 0; i < 4; ++i) acc[mf][nf][i] = 0.f;

    const uint32_t aoff = (lane & 15) * 48 + (lane >> 4) * 16;
    const uint32_t boff = (lane & 7) * 272 + (lane >> 3) * 16 + wn * 2;

    fill(0, 0); fill(1, 16); fill(2, 32);
#pragma unroll 1
    for (int kc = 0; kc < 16; ++kc) {
        __pipeline_wait_prior(2);
        __syncthreads();
        if (kc + 3 < 16) fill((kc + 3) & 3, (kc + 3) << 4);
        else __pipeline_commit();
        const uint32_t asb = sA + ((kc & 3) * QA_T) * 4 + aoff;
        const uint32_t bsb = sB + ((kc & 3) * QB_T) * 4 + boff;

        uint32_t af[4][4], bf[2][4];
#pragma unroll
        for (int mf = 0; mf < 4; ++mf)
            ldsm4(af[mf][0], af[mf][1], af[mf][2], af[mf][3],
                  asb + (wm + mf * 16) * 48);
#pragma unroll
        for (int j = 0; j < 2; ++j)
            ldsm4t(bf[j][0], bf[j][1], bf[j][2], bf[j][3],
                   bsb + (j * 8) * 272);
#pragma unroll
        for (int mf = 0; mf < 4; ++mf)
#pragma unroll
            for (int nf = 0; nf < 4; ++nf)
                mma_bf16(acc[mf][nf][0], acc[mf][nf][1],
                         acc[mf][nf][2], acc[mf][nf][3],
                         af[mf][0], af[mf][1], af[mf][2], af[mf][3],
                         bf[0][nf], bf[1][nf]);
    }

#pragma unroll
    for (int mf = 0; mf < 4; ++mf) {
        const int r0 = m0 + wm + mf * 16 + qr;
        const float bs0 = bias[r0], bs1 = bias[r0 + 8];
#pragma unroll
        for (int nf = 0; nf < 4; ++nf) {
            const int col = n0 + wn + nf * 8 + 2 * qc;
            float o0 = acc[mf][nf][0] + bs0;
            float o1 = acc[mf][nf][1] + bs0;
            float o2 = acc[mf][nf][2] + bs1;
            float o3 = acc[mf][nf][3] + bs1;
            if (MODE == 1) {
                const float* Rb = R + (size_t)bz * M * N;
                const float* rp0 = &Rb[(size_t)r0 * N + col];
                const float* rp1 = &Rb[(size_t)(r0 + 8) * N + col];
                o0 += rp0[0]; o1 += rp0[1]; o2 += rp1[0]; o3 += rp1[1];
                float* Cb = (float*)CoutV + (size_t)bz * M * N;
                float2 lo; lo.x = o0; lo.y = o1;
                float2 hi; hi.x = o2; hi.y = o3;
                *(float2*)&Cb[(size_t)r0 * N + col] = lo;
                *(float2*)&Cb[(size_t)(r0 + 8) * N + col] = hi;
            } else {
                uint32_t* Cb = (uint32_t*)CoutV + (size_t)bz * M * N / 2;
                Cb[(size_t)r0 * 2048 + (col >> 1)] = packbf(o0, o1);
                Cb[(size_t)(r0 + 8) * 2048 + (col >> 1)] = packbf(o2, o3);
            }
        }
    }
}

// ------------ launch 4: attention partials (split-K over keys, 2 halves)
// Round-11 kk body (fastest). Each CTA: 128 q x 2048 keys (16 tiles).
// Writes unnormalized fp32 o and row-sum l to scratch.
#define AP   68
#define AT   (64 * AP)
#define ABUF (2 * AT)
#define ASM_WORDS (2 * ABUF)

__device__ __forceinline__ void a_fill(
    uint32_t* sm, const uint32_t* kz, const uint32_t* vz, int buf, int j0, int tid)
{
    uint32_t* kbuf = sm + buf * ABUF;
    uint32_t* vbuf = kbuf + AT;
#pragma unroll
    for (int i = 0; i < 4; ++i) {
        int lin = tid + i * 256;
        int row = lin >> 4, ch = (lin & 15) << 2;
        __pipeline_memcpy_async(kbuf + row * AP + ch,
                                kz + (size_t)row * 2048 + (j0 >> 1) + ch, 16);
    }
#pragma unroll
    for (int i = 0; i < 4; ++i) {
        int lin = tid + i * 256;
        int row = lin >> 4, ch = (lin & 15) << 2;
        __pipeline_memcpy_async(vbuf + row * AP + ch,
                                vz + (size_t)row * 2048 + (j0 >> 1) + ch, 16);
    }
    __pipeline_commit();
}

__global__ void __launch_bounds__(256, 2) attn_mma_kernel(
    const uint32_t* __restrict__ qkvb, float* __restrict__ po,
    float* __restrict__ pl)
{
    extern __shared__ uint32_t sm[];
    const uint32_t sbase = smem_u32(sm);
    const int tid = threadIdx.x;
    const int lane = tid & 31, w = tid >> 5;
    const int qr = lane >> 2, qc = lane & 3;
    const int i0 = blockIdx.x * 128, h = blockIdx.y;
    const int b = blockIdx.z >> 1, ks = blockIdx.z & 1;
    const int t0 = ks * 16;

    const unsigned short* qp16 =
        (const unsigned short*)qkvb + ((size_t)b * 3 * C + h * DIM) * NPIX;
    const uint32_t* kz = qkvb + ((size_t)b * 3 * C + C + h * DIM) * 2048;
    const uint32_t* vz = qkvb + ((size_t)b * 3 * C + 2 * C + h * DIM) * 2048;

    const float QS = 0.125f * 1.44269504088896341f;
    const int q0 = i0 + w * 16 + qr;
    uint32_t qa[4][4];
#pragma unroll
    for (int kbk = 0; kbk < 4; ++kbk) {
        const int d0 = kbk * 16 + 2 * qc;
#pragma unroll
        for (int half = 0; half < 2; ++half) {
            const int d = d0 + half * 8;
            qa[kbk][half * 2 + 0] =
                packbf(ubf(qp16[(size_t)d * NPIX + q0]) * QS,
                       ubf(qp16[(size_t)(d + 1) * NPIX + q0]) * QS);
            qa[kbk][half * 2 + 1] =
                packbf(ubf(qp16[(size_t)d * NPIX + q0 + 8]) * QS,
                       ubf(qp16[(size_t)(d + 1) * NPIX + q0 + 8]) * QS);
        }
    }

    float oc[8][4];
#pragma unroll
    for (int nv = 0; nv < 8; ++nv)
#pragma unroll
        for (int i = 0; i < 4; ++i) oc[nv][i] = 0.f;
    float l0 = 0.f, l1 = 0.f;

    const uint32_t lmoff = lane * AP * 4;

    a_fill(sm, kz, vz, 0, t0 << 7, tid);

#pragma unroll 1
    for (int tt = 0; tt < 16; ++tt) {
        __pipeline_wait_prior(0);
        __syncthreads();
        if (tt + 1 < 16) a_fill(sm, kz, vz, (tt + 1) & 1, (t0 + tt + 1) << 7, tid);

        const uint32_t ksb = sbase + ((tt & 1) * ABUF) * 4 + lmoff;
        const uint32_t vsb = ksb + AT * 4;

#pragma unroll
        for (int kk = 0; kk < 8; ++kk) {
            uint32_t kf[2][8];
#pragma unroll
            for (int j = 0; j < 2; ++j) {
                const uint32_t rb = ksb + (kk * 16 + j * 8) * 2;
                ldsm4t(kf[j][0], kf[j][1], kf[j][2], kf[j][3], rb);
                ldsm4t(kf[j][4], kf[j][5], kf[j][6], kf[j][7], rb + 32 * AP * 4);
            }
            float c[2][4] = {};
#pragma unroll
            for (int j = 0; j < 2; ++j)
#pragma unroll
                for (int kbk = 0; kbk < 4; ++kbk)
                    mma_bf16(c[j][0], c[j][1], c[j][2], c[j][3],
                             qa[kbk][0], qa[kbk][1], qa[kbk][2], qa[kbk][3],
                             kf[j][2 * kbk], kf[j][2 * kbk + 1]);

            uint32_t vf[2][8];
#pragma unroll
            for (int j = 0; j < 2; ++j) {
                const uint32_t rb = vsb + (kk * 16 + j * 8) * 2;
                ldsm4(vf[j][0], vf[j][1], vf[j][2], vf[j][3], rb);
                ldsm4(vf[j][4], vf[j][5], vf[j][6], vf[j][7], rb + 32 * AP * 4);
            }

            float p00 = ex2(c[0][0]), p01 = ex2(c[0][1]);
            float p02 = ex2(c[0][2]), p03 = ex2(c[0][3]);
            float p10 = ex2(c[1][0]), p11 = ex2(c[1][1]);
            float p12 = ex2(c[1][2]), p13 = ex2(c[1][3]);
            l0 += (p00 + p01) + (p10 + p11);
            l1 += (p02 + p03) + (p12 + p13);
            const uint32_t a0 = packbf(p00, p01);
            const uint32_t a1 = packbf(p02, p03);
            const uint32_t a2 = packbf(p10, p11);
            const uint32_t a3 = packbf(p12, p13);

#pragma unroll
            for (int nv = 0; nv < 8; ++nv)
                mma_bf16(oc[nv][0], oc[nv][1], oc[nv][2], oc[nv][3],
                         a0, a1, a2, a3, vf[0][nv], vf[1][nv]);
        }
    }

    // row-sum reduce across quad; lane qc==0 writes l
    l0 += __shfl_xor_sync(~0u, l0, 1); l0 += __shfl_xor_sync(~0u, l0, 2);
    l1 += __shfl_xor_sync(~0u, l1, 1); l1 += __shfl_xor_sync(~0u, l1, 2);
    float* lp = pl + (size_t)ks * PL_OFF + ((size_t)b * HEADS + h) * NPIX;
    if (qc == 0) {
        lp[q0] = l0;
        lp[q0 + 8] = l1;
    }

    // write unnormalized partial o (fp32)
    float* pop = po + (size_t)ks * PO_OFF + ((size_t)b * C + h * DIM) * NPIX;
#pragma unroll
    for (int nv = 0; nv < 8; ++nv) {
        const int d = nv * 8 + 2 * qc;
        float2 lo; lo.x = oc[nv][0]; lo.y = oc[nv][1];
        float2 hi; hi.x = oc[nv][2]; hi.y = oc[nv][3];
        // note: pairs (oc0,oc1) are adjacent d at same q — store scalar
        pop[(size_t)d * NPIX + q0]           = oc[nv][0];
        pop[(size_t)(d + 1) * NPIX + q0]     = oc[nv][1];
        pop[(size_t)d * NPIX + q0 + 8]       = oc[nv][2];
        pop[(size_t)(d + 1) * NPIX + q0 + 8] = oc[nv][3];
    }
}

// ------------ launch 5: split-K combine -> bf16 packed [c][pix]
__global__ void __launch_bounds__(256) combine_kernel(
    const float* __restrict__ po, const float* __restrict__ pl,
    uint32_t* __restrict__ aob_u32)
{
    const int i = blockIdx.x * 256 + threadIdx.x;      // pair index
    const int p = i & 2047;                            // pix pair
    const int ch = i >> 11;                            // b*C + c
    const int bh = (ch >> 8) * HEADS + ((ch & 255) >> 6);

    float2 o0 = ((const float2*)po)[i];
    float2 o1 = ((const float2*)(po + PO_OFF))[i];
    const int li = bh * 2048 + p;
    float2 la = ((const float2*)pl)[li];
    float2 lb = ((const float2*)(pl + PL_OFF))[li];
    const float inv0 = 1.0f / (la.x + lb.x);
    const float inv1 = 1.0f / (la.y + lb.y);
    aob_u32[i] = packbf((o0.x + o1.x) * inv0, (o0.y + o1.y) * inv1);
}

// ---------------------------------------------------------------- Launch
extern "C" void kernel_launch(void* const* d_in, const int* in_sizes, int n_in,
                              void* d_out, int out_size)
{
    const float* x      = (const float*)d_in[0];
    const float* gamma  = (const float*)d_in[1];
    const float* beta   = (const float*)d_in[2];
    const float* w_qkv  = (const float*)d_in[3];
    const float* b_qkv  = (const float*)d_in[4];
    const float* w_proj = (const float*)d_in[5];
    const float* b_proj = (const float*)d_in[6];
    float* out = (float*)d_out;

    float *gnp, *po, *pl;
    uint32_t *xnb, *qkvb, *wqb, *wpb;
    unsigned short* aob;
    cudaGetSymbolAddress((void**)&xnb,  g_xnb);
    cudaGetSymbolAddress((void**)&qkvb, g_qkvb);
    cudaGetSymbolAddress((void**)&aob,  g_aob);
    cudaGetSymbolAddress((void**)&wqb,  g_wqb);
    cudaGetSymbolAddress((void**)&wpb,  g_wpb);
    cudaGetSymbolAddress((void**)&gnp,  g_gnp);
    cudaGetSymbolAddress((void**)&po,   g_po);
    cudaGetSymbolAddress((void**)&pl,   g_pl);

    static bool attr_set = false;
    if (!attr_set) {
        cudaFuncSetAttribute(attn_mma_kernel,
                             cudaFuncAttributeMaxDynamicSharedMemorySize,
                             ASM_WORDS * 4);
        attr_set = true;
    }

    // 1: GN partial stats + weight packing
    prep_kernel<<<768, 256>>>(x, w_qkv, w_proj, gnp, wqb, wpb);
    // 2: GN finalize + apply -> xn bf16
    gn_apply_kernel<<<256, 256>>>(x, gamma, beta, gnp, xnb);
    // 3: QKV GEMM (bf16 in, bf16 packed out)
    {
        dim3 g(NPIX / 128, (3 * C) / 128, BATCH);
        bgemm_kernel<0><<<g, 256>>>(wqb, xnb, b_qkv, nullptr, qkvb, 3 * C);
    }
    // 4: attention partials, split-K over key halves (captured by ncu)
    {
        dim3 g(NPIX / 128, HEADS, BATCH * 2);
        attn_mma_kernel<<<g, 256, ASM_WORDS * 4>>>(qkvb, po, pl);
    }
    // 5: combine partials -> attn out bf16
    combine_kernel<<<(BATCH * C * NPIX / 2) / 256, 256>>>(po, pl, (uint32_t*)aob);
    // 6: proj GEMM (bf16 in) + bias + residual -> fp32 out
    {
        dim3 g(NPIX / 128, C / 128, BATCH);
        bgemm_kernel<1><<<g, 256>>>(wpb, (const uint32_t*)aob, b_proj, x, out, C);
    }
}